// round 7
// baseline (speedup 1.0000x reference)
#include <cuda_runtime.h>

// Shapes (fixed): B=1024, n=C*H*W=3072, c=10, m=9
#define NN 3072
#define CC 10
#define MM 9
#define BS 4                 // samples per block in the main kernel
#define MAX_B 8192

#define EPS2_INV 100.0f      // 1/EPSILON^2, EPSILON=0.1
#define NSTAB 1e-4f
#define SCALE 0.999f         // 1 - c*NUM_STAB

// Scratch (static device arrays — no allocation)
__device__ float g_M[CC * CC];        // W^T W
__device__ float g_reg[MAX_B];        // per-sample reg
__device__ unsigned int g_count = 0;  // last-block-done counter

// ---------------------------------------------------------------------------
// 1) M = W^T W, reading W [n,c] row-major directly. 55 blocks = upper triangle.
__global__ void gram_kernel(const float* __restrict__ W) {
    // map blockIdx.x (0..54) -> (l, lp) with l <= lp  (branchless unrolled)
    int pair = blockIdx.x;
    int l = 0, idx = pair;
    #pragma unroll
    for (int q = 0; q < CC; q++) {
        if (idx >= CC - q && l == q) { idx -= CC - q; l = q + 1; }
    }
    int lp = l + idx;

    float s = 0.f;
    for (int j = threadIdx.x; j < NN; j += 256)
        s = fmaf(W[j * CC + l], W[j * CC + lp], s);

    #pragma unroll
    for (int o = 16; o; o >>= 1) s += __shfl_xor_sync(0xffffffffu, s, o);
    __shared__ float red[8];
    if ((threadIdx.x & 31) == 0) red[threadIdx.x >> 5] = s;
    __syncthreads();
    if (threadIdx.x == 0) {
        float tot = 0.f;
        #pragma unroll
        for (int w = 0; w < 8; w++) tot += red[w];
        g_M[l * CC + lp] = tot;
        g_M[lp * CC + l] = tot;
    }
}

// ---------------------------------------------------------------------------
// 2) Main: BS samples/block GEMV (W row-major, coalesced float4), analytic
//    Jacobian epilogue (one sample per warp), fused deterministic finalize.
__global__ __launch_bounds__(256) void isometry_kernel(
    const float* __restrict__ data, const float* __restrict__ W,
    const float* __restrict__ bvec, float* __restrict__ out,
    int out_size, int B) {
    const int b0 = blockIdx.x * BS;
    const int t = threadIdx.x;
    const int warp = t >> 5, lane = t & 31;

    // --- GEMV: acc[s][l] = partial z, W rows streamed as float4 ---
    const float4* x4 = (const float4*)(data + (size_t)b0 * NN);
    const float4* w4 = (const float4*)W;   // W has NN*CC floats; rows of 10

    float acc[BS][CC];
    #pragma unroll
    for (int s = 0; s < BS; s++)
        #pragma unroll
        for (int l = 0; l < CC; l++) acc[s][l] = 0.f;

    #pragma unroll
    for (int it = 0; it < (NN / 4) / 256; it++) {
        const int g = t + it * 256;      // group of 4 consecutive j-rows
        // x: 4 elements per sample — streaming loads (read-once, keep W in L2)
        float xf[BS][4];
        #pragma unroll
        for (int s = 0; s < BS; s++) {
            float4 xv = __ldcs(&x4[s * (NN / 4) + g]);
            xf[s][0] = xv.x; xf[s][1] = xv.y; xf[s][2] = xv.z; xf[s][3] = xv.w;
        }
        // W rows j0..j0+3 = 40 contiguous floats = 10 float4 (16B aligned)
        float wf[40];
        #pragma unroll
        for (int q = 0; q < 10; q++) {
            float4 wv = w4[10 * g + q];
            wf[4 * q + 0] = wv.x; wf[4 * q + 1] = wv.y;
            wf[4 * q + 2] = wv.z; wf[4 * q + 3] = wv.w;
        }
        #pragma unroll
        for (int jj = 0; jj < 4; jj++)
            #pragma unroll
            for (int l = 0; l < CC; l++)
                #pragma unroll
                for (int s = 0; s < BS; s++)
                    acc[s][l] = fmaf(xf[s][jj], wf[jj * CC + l], acc[s][l]);
    }
    // intra-warp reduce
    #pragma unroll
    for (int s = 0; s < BS; s++)
        #pragma unroll
        for (int l = 0; l < CC; l++) {
            float v = acc[s][l];
            #pragma unroll
            for (int o = 16; o; o >>= 1)
                v += __shfl_xor_sync(0xffffffffu, v, o);
            acc[s][l] = v;
        }

    __shared__ float red[8][BS][CC];
    if (lane == 0) {
        #pragma unroll
        for (int s = 0; s < BS; s++)
            #pragma unroll
            for (int l = 0; l < CC; l++) red[warp][s][l] = acc[s][l];
    }
    __syncthreads();

    // --- epilogue: warps 0..BS-1, one sample each ---
    __shared__ float z_sh[BS][CC];
    __shared__ float A_sh[BS][MM][CC];
    __shared__ float AM_sh[BS][MM][CC];

    if (warp < BS && b0 + warp < B) {
        const int smp = warp;
        if (lane < CC) {
            float zz = bvec[lane];
            #pragma unroll
            for (int w = 0; w < 8; w++) zz += red[w][smp][lane];
            z_sh[smp][lane] = zz;
        }
        __syncwarp();

        float z[CC];
        #pragma unroll
        for (int l = 0; l < CC; l++) z[l] = z_sh[smp][l];
        float mz = z[0];
        #pragma unroll
        for (int l = 1; l < CC; l++) mz = fmaxf(mz, z[l]);
        float e[CC], se = 0.f;
        #pragma unroll
        for (int l = 0; l < CC; l++) { e[l] = __expf(z[l] - mz); se += e[l]; }
        float inv = 1.f / se;
        float s_[CC], r[CC];
        #pragma unroll
        for (int l = 0; l < CC; l++) {
            s_[l] = e[l] * inv;
            r[l]  = sqrtf(fmaf(s_[l], SCALE, NSTAB));
        }
        float u = 1.f - r[MM];

        float sumr = 0.f;
        #pragma unroll
        for (int l = 0; l < CC; l++) sumr += r[l];
        float arg = fminf(fmaxf(sumr * 0.31622776601683794f, -1.f), 1.f);
        float delta  = 2.f * acosf(arg);
        float factor = delta * delta / (4.f * u * u) * EPS2_INV;

        if (lane < MM) {
            int k = lane;
            float g1 = SCALE * s_[k] / (r[k] * u);
            float g2 = SCALE * r[k] * s_[MM] / (r[MM] * u * u);
            float gs = g1 + g2;
            #pragma unroll
            for (int l = 0; l < CC; l++) {
                float A = -s_[l] * gs;
                if (l == k)  A += g1;
                if (l == MM) A += g2;
                A_sh[smp][k][l] = A;
            }
        }
        __syncwarp();
        if (lane < MM) {
            #pragma unroll
            for (int lp = 0; lp < CC; lp++) {
                float v = 0.f;
                #pragma unroll
                for (int l = 0; l < CC; l++)
                    v = fmaf(A_sh[smp][lane][l], g_M[l * CC + lp], v);
                AM_sh[smp][lane][lp] = v;
            }
        }
        __syncwarp();

        float ss = 0.f;
        for (int idx = lane; idx < MM * MM; idx += 32) {
            int i = idx / MM, j = idx - i * MM;
            float g = 0.f;
            #pragma unroll
            for (int l = 0; l < CC; l++)
                g = fmaf(AM_sh[smp][i][l], A_sh[smp][j][l], g);
            if (i == j) g -= factor;
            ss = fmaf(g, g, ss);
        }
        #pragma unroll
        for (int o = 16; o; o >>= 1) ss += __shfl_xor_sync(0xffffffffu, ss, o);
        if (lane == 0)
            g_reg[b0 + smp] = sqrtf(ss) * (1.0f / (float)NN);
    }
    __syncthreads();

    // --- fused finalize: last block to finish reduces g_reg deterministically ---
    __shared__ unsigned int isLast;
    if (t == 0) {
        __threadfence();   // publish this block's g_reg writes before counter bump
        isLast = (atomicAdd(&g_count, 1u) == (unsigned)gridDim.x - 1u);
    }
    __syncthreads();
    if (isLast) {
        __threadfence();   // acquire all blocks' g_reg writes
        __shared__ float fred[8];
        float s = 0.f;
        for (int i = t; i < B; i += 256) s += g_reg[i];
        #pragma unroll
        for (int o = 16; o; o >>= 1) s += __shfl_xor_sync(0xffffffffu, s, o);
        if ((t & 31) == 0) fred[t >> 5] = s;
        __syncthreads();
        if (t == 0) {
            float tot = 0.f;
            #pragma unroll
            for (int w = 0; w < 8; w++) tot += fred[w];
            out[0] = tot / (float)B;
            g_count = 0;                     // reset for next graph replay
        }
        for (int i = 1 + t; i < out_size; i += 256) out[i] = 0.0f;
    }
}

// ---------------------------------------------------------------------------
extern "C" void kernel_launch(void* const* d_in, const int* in_sizes, int n_in,
                              void* d_out, int out_size) {
    const float* data = (const float*)d_in[0];   // [B, 3, 32, 32]
    const float* W    = (const float*)d_in[1];   // [3072, 10]
    const float* bvec = (const float*)d_in[2];   // [10]
    float* out = (float*)d_out;

    int B = in_sizes[0] / NN;
    if (B > MAX_B) B = MAX_B;

    gram_kernel<<<(CC * (CC + 1)) / 2, 256>>>(W);
    isometry_kernel<<<(B + BS - 1) / BS, 256>>>(data, W, bvec, out, out_size, B);
}

// round 11
// speedup vs baseline: 1.0152x; 1.0152x over previous
#include <cuda_runtime.h>

// Shapes (fixed): B=1024, n=C*H*W=3072, c=10, m=9
#define NN 3072
#define CC 10
#define MM 9
#define BS 4                 // samples per block in the main kernel
#define MAX_B 8192

#define EPS2_INV 100.0f      // 1/EPSILON^2, EPSILON=0.1
#define NSTAB 1e-4f
#define SCALE 0.999f         // 1 - c*NUM_STAB

// Scratch (static device arrays — no allocation)
__device__ float g_Wt[CC * NN];       // W transposed [c][n], float4-friendly
__device__ float g_M[CC * CC];        // W^T W
__device__ float g_reg[MAX_B];        // per-sample reg
__device__ unsigned int g_count = 0;  // last-block-done counter

// ---------------------------------------------------------------------------
// 1) Prep (single launch, role-split blocks):
//    blocks 0..29  : transpose W [n,c] -> Wt [c,n] (coalesced reads of W)
//    blocks 30..84 : M = W^T W, one upper-triangle pair per block
__global__ void prep_kernel(const float* __restrict__ W) {
    const int blk = blockIdx.x;
    const int t = threadIdx.x;

    if (blk < 30) {
        // transpose: 1024 elements per block, coalesced read of W
        int base = blk * 1024;
        #pragma unroll
        for (int k = 0; k < 4; k++) {
            int idx = base + t + k * 256;          // < 30720 always
            int j = idx / CC, l = idx - j * CC;
            g_Wt[l * NN + j] = W[idx];
        }
        return;
    }

    // gram: map (blk-30) in 0..54 -> (l, lp), l <= lp
    int pair = blk - 30;
    int l = 0, idx = pair;
    #pragma unroll
    for (int q = 0; q < CC; q++) {
        if (idx >= CC - q && l == q) { idx -= CC - q; l = q + 1; }
    }
    int lp = l + idx;

    float s = 0.f;
    for (int j = t; j < NN; j += 256)
        s = fmaf(W[j * CC + l], W[j * CC + lp], s);

    #pragma unroll
    for (int o = 16; o; o >>= 1) s += __shfl_xor_sync(0xffffffffu, s, o);
    __shared__ float red[8];
    if ((t & 31) == 0) red[t >> 5] = s;
    __syncthreads();
    if (t == 0) {
        float tot = 0.f;
        #pragma unroll
        for (int w = 0; w < 8; w++) tot += red[w];
        g_M[l * CC + lp] = tot;
        g_M[lp * CC + l] = tot;
    }
}

// ---------------------------------------------------------------------------
// 2) Main: BS samples/block GEMV (Wt coalesced float4 shared across samples),
//    analytic Jacobian epilogue (one sample per warp), fused finalize.
__global__ __launch_bounds__(256) void isometry_kernel(
    const float* __restrict__ data, const float* __restrict__ bvec,
    float* __restrict__ out, int out_size, int B) {
    const int b0 = blockIdx.x * BS;
    const int t = threadIdx.x;
    const int warp = t >> 5, lane = t & 31;

    // --- GEMV: acc[s][l], all loads lane-contiguous float4 (4 lines/warp) ---
    const float4* x4 = (const float4*)(data + (size_t)b0 * NN);
    const float4* w4 = (const float4*)g_Wt;

    float acc[BS][CC];
    #pragma unroll
    for (int s = 0; s < BS; s++)
        #pragma unroll
        for (int l = 0; l < CC; l++) acc[s][l] = 0.f;

    #pragma unroll
    for (int it = 0; it < (NN / 4) / 256; it++) {
        const int j4 = t + it * 256;
        float4 xv[BS];
        #pragma unroll
        for (int s = 0; s < BS; s++)
            xv[s] = __ldcs(&x4[s * (NN / 4) + j4]);   // streaming: read-once
        #pragma unroll
        for (int l = 0; l < CC; l++) {
            float4 wv = w4[l * (NN / 4) + j4];
            #pragma unroll
            for (int s = 0; s < BS; s++) {
                acc[s][l] = fmaf(xv[s].x, wv.x, acc[s][l]);
                acc[s][l] = fmaf(xv[s].y, wv.y, acc[s][l]);
                acc[s][l] = fmaf(xv[s].z, wv.z, acc[s][l]);
                acc[s][l] = fmaf(xv[s].w, wv.w, acc[s][l]);
            }
        }
    }
    // intra-warp reduce the BS*CC accumulators
    #pragma unroll
    for (int s = 0; s < BS; s++)
        #pragma unroll
        for (int l = 0; l < CC; l++) {
            float v = acc[s][l];
            #pragma unroll
            for (int o = 16; o; o >>= 1)
                v += __shfl_xor_sync(0xffffffffu, v, o);
            acc[s][l] = v;
        }

    __shared__ float red[8][BS][CC];
    if (lane == 0) {
        #pragma unroll
        for (int s = 0; s < BS; s++)
            #pragma unroll
            for (int l = 0; l < CC; l++) red[warp][s][l] = acc[s][l];
    }
    __syncthreads();

    // --- epilogue: warps 0..BS-1, one sample each ---
    __shared__ float z_sh[BS][CC];
    __shared__ float A_sh[BS][MM][CC];
    __shared__ float AM_sh[BS][MM][CC];

    if (warp < BS && b0 + warp < B) {
        const int smp = warp;
        if (lane < CC) {
            float zz = bvec[lane];
            #pragma unroll
            for (int w = 0; w < 8; w++) zz += red[w][smp][lane];
            z_sh[smp][lane] = zz;
        }
        __syncwarp();

        float z[CC];
        #pragma unroll
        for (int l = 0; l < CC; l++) z[l] = z_sh[smp][l];
        float mz = z[0];
        #pragma unroll
        for (int l = 1; l < CC; l++) mz = fmaxf(mz, z[l]);
        float e[CC], se = 0.f;
        #pragma unroll
        for (int l = 0; l < CC; l++) { e[l] = __expf(z[l] - mz); se += e[l]; }
        float inv = 1.f / se;
        float s_[CC], r[CC];
        #pragma unroll
        for (int l = 0; l < CC; l++) {
            s_[l] = e[l] * inv;
            r[l]  = sqrtf(fmaf(s_[l], SCALE, NSTAB));
        }
        float u = 1.f - r[MM];

        float sumr = 0.f;
        #pragma unroll
        for (int l = 0; l < CC; l++) sumr += r[l];
        float arg = fminf(fmaxf(sumr * 0.31622776601683794f, -1.f), 1.f);
        float delta  = 2.f * acosf(arg);
        float factor = delta * delta / (4.f * u * u) * EPS2_INV;

        if (lane < MM) {
            int k = lane;
            float g1 = SCALE * s_[k] / (r[k] * u);
            float g2 = SCALE * r[k] * s_[MM] / (r[MM] * u * u);
            float gs = g1 + g2;
            #pragma unroll
            for (int l = 0; l < CC; l++) {
                float A = -s_[l] * gs;
                if (l == k)  A += g1;
                if (l == MM) A += g2;
                A_sh[smp][k][l] = A;
            }
        }
        __syncwarp();
        if (lane < MM) {
            #pragma unroll
            for (int lp = 0; lp < CC; lp++) {
                float v = 0.f;
                #pragma unroll
                for (int l = 0; l < CC; l++)
                    v = fmaf(A_sh[smp][lane][l], g_M[l * CC + lp], v);
                AM_sh[smp][lane][lp] = v;
            }
        }
        __syncwarp();

        float ss = 0.f;
        for (int idx = lane; idx < MM * MM; idx += 32) {
            int i = idx / MM, j = idx - i * MM;
            float g = 0.f;
            #pragma unroll
            for (int l = 0; l < CC; l++)
                g = fmaf(AM_sh[smp][i][l], A_sh[smp][j][l], g);
            if (i == j) g -= factor;
            ss = fmaf(g, g, ss);
        }
        #pragma unroll
        for (int o = 16; o; o >>= 1) ss += __shfl_xor_sync(0xffffffffu, ss, o);
        if (lane == 0)
            g_reg[b0 + smp] = sqrtf(ss) * (1.0f / (float)NN);
    }
    __syncthreads();

    // --- fused finalize: last block reduces g_reg deterministically ---
    __shared__ unsigned int isLast;
    if (t == 0) {
        __threadfence();   // publish this block's g_reg writes
        isLast = (atomicAdd(&g_count, 1u) == (unsigned)gridDim.x - 1u);
    }
    __syncthreads();
    if (isLast) {
        __threadfence();   // order after counter observation
        __shared__ float fred[8];
        float s = 0.f;
        for (int i = t; i < B; i += 256)
            s += __ldcg(&g_reg[i]);          // L2-fresh reads of other CTAs' results
        #pragma unroll
        for (int o = 16; o; o >>= 1) s += __shfl_xor_sync(0xffffffffu, s, o);
        if ((t & 31) == 0) fred[t >> 5] = s;
        __syncthreads();
        if (t == 0) {
            float tot = 0.f;
            #pragma unroll
            for (int w = 0; w < 8; w++) tot += fred[w];
            out[0] = tot / (float)B;
            g_count = 0;                     // reset for next graph replay
        }
        for (int i = 1 + t; i < out_size; i += 256) out[i] = 0.0f;
    }
}

// ---------------------------------------------------------------------------
extern "C" void kernel_launch(void* const* d_in, const int* in_sizes, int n_in,
                              void* d_out, int out_size) {
    const float* data = (const float*)d_in[0];   // [B, 3, 32, 32]
    const float* W    = (const float*)d_in[1];   // [3072, 10]
    const float* bvec = (const float*)d_in[2];   // [10]
    float* out = (float*)d_out;

    int B = in_sizes[0] / NN;
    if (B > MAX_B) B = MAX_B;

    prep_kernel<<<30 + (CC * (CC + 1)) / 2, 256>>>(W);
    isometry_kernel<<<(B + BS - 1) / BS, 256>>>(data, bvec, out, out_size, B);
}